// round 14
// baseline (speedup 1.0000x reference)
#include <cuda_runtime.h>
#include <cuda_fp16.h>
#include <cstdint>

#define BB 2
#define TT 2048
#define CCH 2048
#define NH 16
#define NKV 4
#define HD 128
#define MTOT 4096
#define NQKV 3072

// ---- scratch (no cudaMalloc allowed) ----
__device__ __half g_xh[(size_t)MTOT*CCH];      // x fp16 [m][k]
__device__ __half g_wqkv[(size_t)NQKV*CCH];    // W^T fp16 [n][k]
__device__ __half g_wo[(size_t)CCH*CCH];       // Wo^T fp16 [n][k]
__device__ __half g_ah[(size_t)MTOT*CCH];      // attn out fp16 [m][k]
__device__ __half g_qh[(size_t)BB*NH*TT*HD];
__device__ __half g_kh[(size_t)BB*NKV*TT*HD];
__device__ __half g_vh[(size_t)BB*NKV*TT*HD];

// ---------------------------------------------------------------------------
// Conversion kernels
// ---------------------------------------------------------------------------
__global__ void cvt_x_kernel(const float* __restrict__ x) {
    const size_t i = (size_t)blockIdx.x * 256 + threadIdx.x;
    const float4 v = ((const float4*)x)[i];
    ((__half2*)g_xh)[2 * i]     = __floats2half2_rn(v.x, v.y);
    ((__half2*)g_xh)[2 * i + 1] = __floats2half2_rn(v.z, v.w);
}

__global__ void t_wqkv(const float* __restrict__ Wq,
                       const float* __restrict__ Wk,
                       const float* __restrict__ Wv) {
    __shared__ float tile[32][33];
    const int n0 = blockIdx.x * 32, k0 = blockIdx.y * 32;
    const int tx = threadIdx.x & 31, ty = threadIdx.x >> 5;
#pragma unroll
    for (int p = 0; p < 4; ++p) {
        const int r = ty + p * 8;
        const int n = n0 + tx;
        float v;
        if (n0 < 2048)      v = Wq[(size_t)(k0 + r) * 2048 + n];
        else if (n0 < 2560) v = Wk[(size_t)(k0 + r) * 512 + (n - 2048)];
        else                v = Wv[(size_t)(k0 + r) * 512 + (n - 2560)];
        tile[r][tx] = v;
    }
    __syncthreads();
#pragma unroll
    for (int p = 0; p < 4; ++p) {
        const int a = ty + p * 8;
        g_wqkv[(size_t)(n0 + a) * 2048 + k0 + tx] = __float2half(tile[tx][a]);
    }
}

__global__ void t_wo(const float* __restrict__ Wo) {
    __shared__ float tile[32][33];
    const int n0 = blockIdx.x * 32, k0 = blockIdx.y * 32;
    const int tx = threadIdx.x & 31, ty = threadIdx.x >> 5;
#pragma unroll
    for (int p = 0; p < 4; ++p) {
        const int r = ty + p * 8;
        tile[r][tx] = Wo[(size_t)(k0 + r) * 2048 + n0 + tx];
    }
    __syncthreads();
#pragma unroll
    for (int p = 0; p < 4; ++p) {
        const int a = ty + p * 8;
        g_wo[(size_t)(n0 + a) * 2048 + k0 + tx] = __float2half(tile[tx][a]);
    }
}

// ---------------------------------------------------------------------------
// Helpers
// ---------------------------------------------------------------------------
__device__ __forceinline__ uint32_t smem_u32(const void* p) {
    return (uint32_t)__cvta_generic_to_shared(p);
}
__device__ __forceinline__ void ldm_x4(unsigned r[4], const void* p) {
    uint32_t a = smem_u32(p);
    asm volatile("ldmatrix.sync.aligned.m8n8.x4.shared.b16 {%0,%1,%2,%3}, [%4];"
        : "=r"(r[0]), "=r"(r[1]), "=r"(r[2]), "=r"(r[3]) : "r"(a));
}
__device__ __forceinline__ void ldm_x4_t(unsigned r[4], const void* p) {
    uint32_t a = smem_u32(p);
    asm volatile("ldmatrix.sync.aligned.m8n8.x4.trans.shared.b16 {%0,%1,%2,%3}, [%4];"
        : "=r"(r[0]), "=r"(r[1]), "=r"(r[2]), "=r"(r[3]) : "r"(a));
}
__device__ __forceinline__ void mma16816h(float c[4],
    unsigned a0, unsigned a1, unsigned a2, unsigned a3, unsigned b0, unsigned b1)
{
    asm volatile(
        "mma.sync.aligned.m16n8k16.row.col.f32.f16.f16.f32 "
        "{%0,%1,%2,%3},{%4,%5,%6,%7},{%8,%9},{%0,%1,%2,%3};"
        : "+f"(c[0]), "+f"(c[1]), "+f"(c[2]), "+f"(c[3])
        : "r"(a0), "r"(a1), "r"(a2), "r"(a3), "r"(b0), "r"(b1));
}
__device__ __forceinline__ unsigned packf16(float lo, float hi) {
    unsigned d;
    asm("cvt.rn.f16x2.f32 %0, %1, %2;" : "=r"(d) : "f"(hi), "f"(lo));
    return d;
}
__device__ __forceinline__ float ex2(float x) {
    float y; asm("ex2.approx.f32 %0, %1;" : "=f"(y) : "f"(x)); return y;
}
__device__ __forceinline__ void cpasync16(uint32_t smem, const void* gmem) {
    asm volatile("cp.async.cg.shared.global [%0], [%1], 16;" :: "r"(smem), "l"(gmem));
}
#define CP_COMMIT() asm volatile("cp.async.commit_group;")
template<int N> __device__ __forceinline__ void cp_wait() {
    asm volatile("cp.async.wait_group %0;" :: "n"(N));
}

// ---------------------------------------------------------------------------
// Plain fp16 GEMM: CTA 128(M) x 256(N), BK=128, 256 threads (8 warps 2x4,
// warp tile 64x64). 2-stage cp.async ring. MODE 0 fuses RoPE (+Q scale) in
// the epilogue via an fp32 smem stage (ring smem reused).
// ---------------------------------------------------------------------------
#define SPITCH 136                      // 128 + 8 pad halves (272B rows)
#define A_OFF 0
#define B_OFF (128 * SPITCH)
#define STG_HALVES (384 * SPITCH)
#define G_SMEM_BYTES (2 * STG_HALVES * 2)   // ~204 KB
#define CPIT 264                        // fp32 staging pitch (256 + 8)

template<int MODE>
__global__ __launch_bounds__(256, 1) void gemm_f16(float* __restrict__ out,
                                                   const float* __restrict__ cosp,
                                                   const float* __restrict__ sinp)
{
    extern __shared__ __half sgm[];

    const int tid  = threadIdx.x;
    const int lane = tid & 31;
    const int wid  = tid >> 5;
    const int bm = blockIdx.y * 128;
    const int bn = blockIdx.x * 256;
    const int mw = (wid >> 2) * 64;
    const int nw = (wid & 3) * 64;

    const __half* Ax = (MODE == 0) ? g_xh : g_ah;
    const __half* Bw = (MODE == 0) ? g_wqkv : g_wo;

    const uint32_t sb = smem_u32(sgm);

#define ISSUE(kt)                                                               \
    do {                                                                        \
        const int _k0 = (kt) * 128;                                             \
        const uint32_t _st = sb + (((kt) & 1) * STG_HALVES) * 2;                \
        _Pragma("unroll")                                                       \
        for (int _i = 0; _i < 8; ++_i) {                                        \
            const int _idx = _i * 256 + tid;                                    \
            const int _r = _idx >> 4, _c = (_idx & 15) * 8;                     \
            cpasync16(_st + (A_OFF + _r * SPITCH + _c) * 2,                     \
                      Ax + (size_t)(bm + _r) * CCH + _k0 + _c);                 \
        }                                                                       \
        _Pragma("unroll")                                                       \
        for (int _i = 0; _i < 16; ++_i) {                                       \
            const int _idx = _i * 256 + tid;                                    \
            const int _r = _idx >> 4, _c = (_idx & 15) * 8;                     \
            cpasync16(_st + (B_OFF + _r * SPITCH + _c) * 2,                     \
                      Bw + (size_t)(bn + _r) * CCH + _k0 + _c);                 \
        }                                                                       \
        CP_COMMIT();                                                            \
    } while (0)

    float c[4][8][4];
#pragma unroll
    for (int i = 0; i < 4; ++i)
#pragma unroll
        for (int j = 0; j < 8; ++j)
#pragma unroll
            for (int e = 0; e < 4; ++e) c[i][j][e] = 0.f;

    ISSUE(0);

    const int arow = ((lane >> 3) & 1) * 8 + (lane & 7);
    const int acol = (lane >> 4) * 8;
    const int brow = (lane >> 4) * 8 + (lane & 7);
    const int bcol = ((lane >> 3) & 1) * 8;

    const int NKT = CCH / 128;   // 16
    for (int kt = 0; kt < NKT; ++kt) {
        if (kt + 1 < NKT) { ISSUE(kt + 1); cp_wait<1>(); }
        else              { cp_wait<0>(); }
        __syncthreads();

        __half* st = sgm + (kt & 1) * STG_HALVES;
#pragma unroll
        for (int kk = 0; kk < 8; ++kk) {
            unsigned af[4][4], bf[4][4];
#pragma unroll
            for (int mi = 0; mi < 4; ++mi)
                ldm_x4(af[mi], st + A_OFF + (mw + mi * 16 + arow) * SPITCH + kk * 16 + acol);
#pragma unroll
            for (int x = 0; x < 4; ++x)
                ldm_x4(bf[x], st + B_OFF + (nw + x * 16 + brow) * SPITCH + kk * 16 + bcol);
#pragma unroll
            for (int mi = 0; mi < 4; ++mi) {
#pragma unroll
                for (int nj = 0; nj < 8; ++nj) {
                    const int x = nj >> 1, y = (nj & 1) * 2;
                    mma16816h(c[mi][nj], af[mi][0], af[mi][1], af[mi][2], af[mi][3],
                              bf[x][y], bf[x][y + 1]);
                }
            }
        }
        __syncthreads();
    }

    if (MODE == 1) {
        // plain fp32 epilogue
#pragma unroll
        for (int mi = 0; mi < 4; ++mi) {
#pragma unroll
            for (int nj = 0; nj < 8; ++nj) {
                const int m = bm + mw + mi * 16 + (lane >> 2);
                const int n = bn + nw + nj * 8 + 2 * (lane & 3);
                *(float2*)(out + (size_t)m * 2048 + n) =
                    make_float2(c[mi][nj][0], c[mi][nj][1]);
                *(float2*)(out + (size_t)(m + 8) * 2048 + n) =
                    make_float2(c[mi][nj][2], c[mi][nj][3]);
            }
        }
    } else {
        // fused-RoPE epilogue: stage fp32 tile in smem, then rope + fp16 store
        float* sC = (float*)sgm;   // 128 x CPIT fp32 (135 KB <= ring)
#pragma unroll
        for (int mi = 0; mi < 4; ++mi) {
#pragma unroll
            for (int nj = 0; nj < 8; ++nj) {
                const int ml = mw + mi * 16 + (lane >> 2);
                const int nl = nw + nj * 8 + 2 * (lane & 3);
                sC[ml * CPIT + nl]           = c[mi][nj][0];
                sC[ml * CPIT + nl + 1]       = c[mi][nj][1];
                sC[(ml + 8) * CPIT + nl]     = c[mi][nj][2];
                sC[(ml + 8) * CPIT + nl + 1] = c[mi][nj][3];
            }
        }
        __syncthreads();

        const bool isQ = (bn < 2048);
        const bool isK = (bn >= 2048) && (bn < 2560);
        const float SC = 0.08838834764831845f * 1.44269504088896341f;

        for (int idx = tid; idx < 128 * 128; idx += 256) {
            const int ml = idx >> 7;         // local row
            const int dp = idx & 127;        // pair index across 2 heads
            const int hs = dp >> 6;          // head-half select (0/1)
            const int d  = dp & 63;
            const int m = bm + ml;
            const int b = m >> 11, t = m & 2047;
            const float x0 = sC[ml * CPIT + hs * 128 + d];
            const float x1 = sC[ml * CPIT + hs * 128 + d + 64];

            if (isQ) {
                const float c0 = cosp[t * HD + d],      s0 = sinp[t * HD + d];
                const float c1 = cosp[t * HD + d + 64], s1 = sinp[t * HD + d + 64];
                const int h = (bn >> 7) + hs;
                __half* dst = g_qh + ((size_t)(b * NH + h) * TT + t) * HD;
                dst[d]      = __float2half((x0 * c0 - x1 * s0) * SC);
                dst[d + 64] = __float2half((x1 * c1 + x0 * s1) * SC);
            } else if (isK) {
                const float c0 = cosp[t * HD + d],      s0 = sinp[t * HD + d];
                const float c1 = cosp[t * HD + d + 64], s1 = sinp[t * HD + d + 64];
                const int kvh = ((bn - 2048) >> 7) + hs;
                __half* dst = g_kh + ((size_t)(b * NKV + kvh) * TT + t) * HD;
                dst[d]      = __float2half(x0 * c0 - x1 * s0);
                dst[d + 64] = __float2half(x1 * c1 + x0 * s1);
            } else {
                const int kvh = ((bn - 2560) >> 7) + hs;
                __half* dst = g_vh + ((size_t)(b * NKV + kvh) * TT + t) * HD;
                dst[d]      = __float2half(x0);
                dst[d + 64] = __float2half(x1);
            }
        }
    }
}

// ---------------------------------------------------------------------------
// Tensor-core flash attention: 128 q-rows x 128-key tiles, 2-stage cp.async
// ring (unchanged from R12).
// ---------------------------------------------------------------------------
#define APITCH 136
#define KS_ROW 128
#define VS_ROW (128 + 2 * 128)
#define ATT_SMEM_BYTES (640 * APITCH * 2)

__global__ __launch_bounds__(256, 1) void attn_tc()
{
    extern __shared__ __half sh2[];
    __half* sQ = sh2;

    const int tid = threadIdx.x;
    const int wid = tid >> 5, lane = tid & 31;
    const int r = lane >> 2, cq = lane & 3;
    const int qt = (int)gridDim.x - 1 - (int)blockIdx.x;
    const int bh = blockIdx.y;
    const int b = bh >> 4, h = bh & 15, kvh = h >> 2;

    const uint4* qg = (const uint4*)(g_qh + (size_t)bh * TT * HD + (size_t)qt * 128 * HD);
    const __half* kgp = g_kh + (size_t)(b * NKV + kvh) * TT * HD;
    const __half* vgp = g_vh + (size_t)(b * NKV + kvh) * TT * HD;
    const uint32_t sbatt = smem_u32(sh2);

#define ISSUE_KV(kt)                                                            \
    do {                                                                        \
        const int _s = (kt) & 1;                                                \
        _Pragma("unroll")                                                       \
        for (int _i = 0; _i < 8; ++_i) {                                        \
            const int _idx = _i * 256 + tid;                                    \
            const int _r = _idx >> 4, _c = (_idx & 15) * 8;                     \
            cpasync16(sbatt + ((KS_ROW + _s * 128 + _r) * APITCH + _c) * 2,     \
                      kgp + (size_t)((kt) * 128 + _r) * HD + _c);               \
            cpasync16(sbatt + ((VS_ROW + _s * 128 + _r) * APITCH + _c) * 2,     \
                      vgp + (size_t)((kt) * 128 + _r) * HD + _c);               \
        }                                                                       \
        CP_COMMIT();                                                            \
    } while (0)

#pragma unroll
    for (int it = 0; it < 8; ++it) {
        const int idx = it * 256 + tid;
        *(uint4*)&sQ[(idx >> 4) * APITCH + (idx & 15) * 8] = qg[idx];
    }

    const int ntiles = qt + 1;
    ISSUE_KV(0);
    if (ntiles > 1) ISSUE_KV(1);
    __syncthreads();

    unsigned qf[8][4];
    {
        const int arow = wid * 16 + (lane & 15);
        const int acol = (lane >> 4) * 8;
#pragma unroll
        for (int kk = 0; kk < 8; ++kk)
            ldm_x4(qf[kk], sQ + arow * APITCH + kk * 16 + acol);
    }

    float o[16][4];
#pragma unroll
    for (int nj = 0; nj < 16; ++nj)
#pragma unroll
        for (int e = 0; e < 4; ++e) o[nj][e] = 0.f;
    float m0 = -1e30f, m1 = -1e30f, l0 = 0.f, l1 = 0.f;

    const int krow = (lane & 7) + ((lane >> 4) << 3);
    const int kcol = ((lane >> 3) & 1) * 8;
    const int vrow = lane & 15;
    const int vcol = (lane >> 4) * 8;

    for (int kt = 0; kt < ntiles; ++kt) {
        if (kt + 1 < ntiles) cp_wait<1>();
        else                 cp_wait<0>();
        __syncthreads();

        __half* sK = sh2 + (KS_ROW + (kt & 1) * 128) * APITCH;
        __half* sV = sh2 + (VS_ROW + (kt & 1) * 128) * APITCH;

        float s[16][4];
#pragma unroll
        for (int nj = 0; nj < 16; ++nj)
#pragma unroll
            for (int e = 0; e < 4; ++e) s[nj][e] = 0.f;

#pragma unroll
        for (int kk = 0; kk < 8; ++kk) {
#pragma unroll
            for (int nb = 0; nb < 8; ++nb) {
                unsigned kf[4];
                ldm_x4(kf, sK + (nb * 16 + krow) * APITCH + kk * 16 + kcol);
                mma16816h(s[nb * 2],     qf[kk][0], qf[kk][1], qf[kk][2], qf[kk][3], kf[0], kf[1]);
                mma16816h(s[nb * 2 + 1], qf[kk][0], qf[kk][1], qf[kk][2], qf[kk][3], kf[2], kf[3]);
            }
        }

        if (kt + 1 == ntiles) {
            const int row0 = qt * 128 + wid * 16 + r;
#pragma unroll
            for (int nj = 0; nj < 16; ++nj) {
                const int key = kt * 128 + nj * 8 + 2 * cq;
                if (key > row0)         s[nj][0] = -1e30f;
                if (key + 1 > row0)     s[nj][1] = -1e30f;
                if (key > row0 + 8)     s[nj][2] = -1e30f;
                if (key + 1 > row0 + 8) s[nj][3] = -1e30f;
            }
        }

        float mx0 = s[0][0], mx1 = s[0][2];
#pragma unroll
        for (int nj = 0; nj < 16; ++nj) {
            mx0 = fmaxf(mx0, fmaxf(s[nj][0], s[nj][1]));
            mx1 = fmaxf(mx1, fmaxf(s[nj][2], s[nj][3]));
        }
        mx0 = fmaxf(mx0, __shfl_xor_sync(0xffffffffu, mx0, 1));
        mx0 = fmaxf(mx0, __shfl_xor_sync(0xffffffffu, mx0, 2));
        mx1 = fmaxf(mx1, __shfl_xor_sync(0xffffffffu, mx1, 1));
        mx1 = fmaxf(mx1, __shfl_xor_sync(0xffffffffu, mx1, 2));

        const float mn0 = fmaxf(m0, mx0), mn1 = fmaxf(m1, mx1);
        const float cr0 = ex2(m0 - mn0),  cr1 = ex2(m1 - mn1);
        m0 = mn0; m1 = mn1;

        float sum0 = 0.f, sum1 = 0.f;
#pragma unroll
        for (int nj = 0; nj < 16; ++nj) {
            s[nj][0] = ex2(s[nj][0] - mn0); sum0 += s[nj][0];
            s[nj][1] = ex2(s[nj][1] - mn0); sum0 += s[nj][1];
            s[nj][2] = ex2(s[nj][2] - mn1); sum1 += s[nj][2];
            s[nj][3] = ex2(s[nj][3] - mn1); sum1 += s[nj][3];
        }
        sum0 += __shfl_xor_sync(0xffffffffu, sum0, 1);
        sum0 += __shfl_xor_sync(0xffffffffu, sum0, 2);
        sum1 += __shfl_xor_sync(0xffffffffu, sum1, 1);
        sum1 += __shfl_xor_sync(0xffffffffu, sum1, 2);
        l0 = l0 * cr0 + sum0;
        l1 = l1 * cr1 + sum1;

#pragma unroll
        for (int nj = 0; nj < 16; ++nj) {
            o[nj][0] *= cr0; o[nj][1] *= cr0;
            o[nj][2] *= cr1; o[nj][3] *= cr1;
        }

        unsigned p[16][2];
#pragma unroll
        for (int nj = 0; nj < 16; ++nj) {
            p[nj][0] = packf16(s[nj][0], s[nj][1]);
            p[nj][1] = packf16(s[nj][2], s[nj][3]);
        }

#pragma unroll
        for (int kk = 0; kk < 8; ++kk) {
            const unsigned a0 = p[2 * kk][0],     a1 = p[2 * kk][1];
            const unsigned a2 = p[2 * kk + 1][0], a3 = p[2 * kk + 1][1];
#pragma unroll
            for (int db = 0; db < 8; ++db) {
                unsigned vf[4];
                ldm_x4_t(vf, sV + (kk * 16 + vrow) * APITCH + db * 16 + vcol);
                mma16816h(o[db * 2],     a0, a1, a2, a3, vf[0], vf[1]);
                mma16816h(o[db * 2 + 1], a0, a1, a2, a3, vf[2], vf[3]);
            }
        }
        __syncthreads();
        if (kt + 2 < ntiles) ISSUE_KV(kt + 2);
    }

    const float inv0 = 1.f / l0, inv1 = 1.f / l1;
    const int row0 = qt * 128 + wid * 16 + r;
    const size_t base0 = ((size_t)(b * TT + row0)) * CCH + h * HD;
    const size_t base1 = base0 + 8 * CCH;
#pragma unroll
    for (int nj = 0; nj < 16; ++nj) {
        const int d = nj * 8 + 2 * cq;
        *(unsigned*)(g_ah + base0 + d) = packf16(o[nj][0] * inv0, o[nj][1] * inv0);
        *(unsigned*)(g_ah + base1 + d) = packf16(o[nj][2] * inv1, o[nj][3] * inv1);
    }
}

// ---------------------------------------------------------------------------
extern "C" void kernel_launch(void* const* d_in, const int* in_sizes, int n_in,
                              void* d_out, int out_size)
{
    const float* x    = (const float*)d_in[0];
    const float* cosp = (const float*)d_in[1];
    const float* sinp = (const float*)d_in[2];
    const float* Wq   = (const float*)d_in[3];
    const float* Wk   = (const float*)d_in[4];
    const float* Wv   = (const float*)d_in[5];
    const float* Wo   = (const float*)d_in[6];
    float* out = (float*)d_out;

    cudaFuncSetAttribute(attn_tc,
                         cudaFuncAttributeMaxDynamicSharedMemorySize, ATT_SMEM_BYTES);
    cudaFuncSetAttribute(gemm_f16<0>,
                         cudaFuncAttributeMaxDynamicSharedMemorySize, G_SMEM_BYTES);
    cudaFuncSetAttribute(gemm_f16<1>,
                         cudaFuncAttributeMaxDynamicSharedMemorySize, G_SMEM_BYTES);

    // 0. conversions
    cvt_x_kernel<<<(MTOT * CCH / 4) / 256, 256>>>(x);
    t_wqkv<<<dim3(NQKV / 32, CCH / 32), 256>>>(Wq, Wk, Wv);
    t_wo<<<dim3(CCH / 32, CCH / 32), 256>>>(Wo);

    // 1. fused QKV projection + RoPE + Q-scale -> fp16 q/k/v (head-major)
    gemm_f16<0><<<dim3(NQKV / 256, MTOT / 128), 256, G_SMEM_BYTES>>>(nullptr, cosp, sinp);

    // 2. tensor-core causal GQA flash attention (128-key tiles)
    attn_tc<<<dim3(TT / 128, BB * NH), 256, ATT_SMEM_BYTES>>>();

    // 3. output projection
    gemm_f16<1><<<dim3(CCH / 256, MTOT / 128), 256, G_SMEM_BYTES>>>(out, nullptr, nullptr);
}

// round 15
// speedup vs baseline: 1.1090x; 1.1090x over previous
#include <cuda_runtime.h>
#include <cuda_fp16.h>
#include <cstdint>

#define BB 2
#define TT 2048
#define CCH 2048
#define NH 16
#define NKV 4
#define HD 128
#define MTOT 4096
#define NQKV 3072

// ---- scratch (no cudaMalloc allowed) ----
__device__ __half g_xh[(size_t)MTOT*CCH];      // x fp16 [m][k]
__device__ __half g_wqkv[(size_t)NQKV*CCH];    // W^T fp16 [n][k]
__device__ __half g_wo[(size_t)CCH*CCH];       // Wo^T fp16 [n][k]
__device__ __half g_ah[(size_t)MTOT*CCH];      // attn out fp16 [m][k]
__device__ __half g_qh[(size_t)BB*NH*TT*HD];
__device__ __half g_kh[(size_t)BB*NKV*TT*HD];
__device__ __half g_vh[(size_t)BB*NKV*TT*HD];

// ---------------------------------------------------------------------------
// Conversion kernels
// ---------------------------------------------------------------------------
__global__ void cvt_x_kernel(const float* __restrict__ x) {
    const size_t i = (size_t)blockIdx.x * 256 + threadIdx.x;
    const float4 v = ((const float4*)x)[i];
    ((__half2*)g_xh)[2 * i]     = __floats2half2_rn(v.x, v.y);
    ((__half2*)g_xh)[2 * i + 1] = __floats2half2_rn(v.z, v.w);
}

__global__ void t_wqkv(const float* __restrict__ Wq,
                       const float* __restrict__ Wk,
                       const float* __restrict__ Wv) {
    __shared__ float tile[32][33];
    const int n0 = blockIdx.x * 32, k0 = blockIdx.y * 32;
    const int tx = threadIdx.x & 31, ty = threadIdx.x >> 5;
#pragma unroll
    for (int p = 0; p < 4; ++p) {
        const int r = ty + p * 8;
        const int n = n0 + tx;
        float v;
        if (n0 < 2048)      v = Wq[(size_t)(k0 + r) * 2048 + n];
        else if (n0 < 2560) v = Wk[(size_t)(k0 + r) * 512 + (n - 2048)];
        else                v = Wv[(size_t)(k0 + r) * 512 + (n - 2560)];
        tile[r][tx] = v;
    }
    __syncthreads();
#pragma unroll
    for (int p = 0; p < 4; ++p) {
        const int a = ty + p * 8;
        g_wqkv[(size_t)(n0 + a) * 2048 + k0 + tx] = __float2half(tile[tx][a]);
    }
}

__global__ void t_wo(const float* __restrict__ Wo) {
    __shared__ float tile[32][33];
    const int n0 = blockIdx.x * 32, k0 = blockIdx.y * 32;
    const int tx = threadIdx.x & 31, ty = threadIdx.x >> 5;
#pragma unroll
    for (int p = 0; p < 4; ++p) {
        const int r = ty + p * 8;
        tile[r][tx] = Wo[(size_t)(k0 + r) * 2048 + n0 + tx];
    }
    __syncthreads();
#pragma unroll
    for (int p = 0; p < 4; ++p) {
        const int a = ty + p * 8;
        g_wo[(size_t)(n0 + a) * 2048 + k0 + tx] = __float2half(tile[tx][a]);
    }
}

// ---------------------------------------------------------------------------
// Helpers
// ---------------------------------------------------------------------------
__device__ __forceinline__ uint32_t smem_u32(const void* p) {
    return (uint32_t)__cvta_generic_to_shared(p);
}
__device__ __forceinline__ void ldm_x4(unsigned r[4], const void* p) {
    uint32_t a = smem_u32(p);
    asm volatile("ldmatrix.sync.aligned.m8n8.x4.shared.b16 {%0,%1,%2,%3}, [%4];"
        : "=r"(r[0]), "=r"(r[1]), "=r"(r[2]), "=r"(r[3]) : "r"(a));
}
__device__ __forceinline__ void ldm_x4_t(unsigned r[4], const void* p) {
    uint32_t a = smem_u32(p);
    asm volatile("ldmatrix.sync.aligned.m8n8.x4.trans.shared.b16 {%0,%1,%2,%3}, [%4];"
        : "=r"(r[0]), "=r"(r[1]), "=r"(r[2]), "=r"(r[3]) : "r"(a));
}
__device__ __forceinline__ void mma16816h(float c[4],
    unsigned a0, unsigned a1, unsigned a2, unsigned a3, unsigned b0, unsigned b1)
{
    asm volatile(
        "mma.sync.aligned.m16n8k16.row.col.f32.f16.f16.f32 "
        "{%0,%1,%2,%3},{%4,%5,%6,%7},{%8,%9},{%0,%1,%2,%3};"
        : "+f"(c[0]), "+f"(c[1]), "+f"(c[2]), "+f"(c[3])
        : "r"(a0), "r"(a1), "r"(a2), "r"(a3), "r"(b0), "r"(b1));
}
__device__ __forceinline__ unsigned packf16(float lo, float hi) {
    unsigned d;
    asm("cvt.rn.f16x2.f32 %0, %1, %2;" : "=r"(d) : "f"(hi), "f"(lo));
    return d;
}
__device__ __forceinline__ float ex2(float x) {
    float y; asm("ex2.approx.f32 %0, %1;" : "=f"(y) : "f"(x)); return y;
}
__device__ __forceinline__ void cpasync16(uint32_t smem, const void* gmem) {
    asm volatile("cp.async.cg.shared.global [%0], [%1], 16;" :: "r"(smem), "l"(gmem));
}
#define CP_COMMIT() asm volatile("cp.async.commit_group;")
template<int N> __device__ __forceinline__ void cp_wait() {
    asm volatile("cp.async.wait_group %0;" :: "n"(N));
}

// ---------------------------------------------------------------------------
// Plain fp16 GEMM: CTA 128(M) x 256(N), BK=128, 256 threads (8 warps 2x4,
// warp tile 64x64). 2-stage cp.async ring (exact group accounting). R12 code.
// ---------------------------------------------------------------------------
#define SPITCH 136                      // 128 + 8 pad halves (272B rows)
#define A_OFF 0
#define B_OFF (128 * SPITCH)
#define STG_HALVES (384 * SPITCH)
#define G_SMEM_BYTES (2 * STG_HALVES * 2)   // 204 KB

template<int MODE>
__global__ __launch_bounds__(256, 1) void gemm_f16(float* __restrict__ out)
{
    extern __shared__ __half sgm[];

    const int tid  = threadIdx.x;
    const int lane = tid & 31;
    const int wid  = tid >> 5;
    const int bm = blockIdx.y * 128;
    const int bn = blockIdx.x * 256;
    const int mw = (wid >> 2) * 64;
    const int nw = (wid & 3) * 64;

    const __half* Ax = (MODE == 0) ? g_xh : g_ah;
    const __half* Bw = (MODE == 0) ? g_wqkv : g_wo;

    const uint32_t sb = smem_u32(sgm);

#define ISSUE(kt)                                                               \
    do {                                                                        \
        const int _k0 = (kt) * 128;                                             \
        const uint32_t _st = sb + (((kt) & 1) * STG_HALVES) * 2;                \
        _Pragma("unroll")                                                       \
        for (int _i = 0; _i < 8; ++_i) {                                        \
            const int _idx = _i * 256 + tid;                                    \
            const int _r = _idx >> 4, _c = (_idx & 15) * 8;                     \
            cpasync16(_st + (A_OFF + _r * SPITCH + _c) * 2,                     \
                      Ax + (size_t)(bm + _r) * CCH + _k0 + _c);                 \
        }                                                                       \
        _Pragma("unroll")                                                       \
        for (int _i = 0; _i < 16; ++_i) {                                       \
            const int _idx = _i * 256 + tid;                                    \
            const int _r = _idx >> 4, _c = (_idx & 15) * 8;                     \
            cpasync16(_st + (B_OFF + _r * SPITCH + _c) * 2,                     \
                      Bw + (size_t)(bn + _r) * CCH + _k0 + _c);                 \
        }                                                                       \
        CP_COMMIT();                                                            \
    } while (0)

    float c[4][8][4];
#pragma unroll
    for (int i = 0; i < 4; ++i)
#pragma unroll
        for (int j = 0; j < 8; ++j)
#pragma unroll
            for (int e = 0; e < 4; ++e) c[i][j][e] = 0.f;

    ISSUE(0);

    const int arow = ((lane >> 3) & 1) * 8 + (lane & 7);
    const int acol = (lane >> 4) * 8;
    const int brow = (lane >> 4) * 8 + (lane & 7);
    const int bcol = ((lane >> 3) & 1) * 8;

    const int NKT = CCH / 128;   // 16
    for (int kt = 0; kt < NKT; ++kt) {
        if (kt + 1 < NKT) { ISSUE(kt + 1); cp_wait<1>(); }
        else              { cp_wait<0>(); }
        __syncthreads();

        __half* st = sgm + (kt & 1) * STG_HALVES;
#pragma unroll
        for (int kk = 0; kk < 8; ++kk) {
            unsigned af[4][4], bf[4][4];
#pragma unroll
            for (int mi = 0; mi < 4; ++mi)
                ldm_x4(af[mi], st + A_OFF + (mw + mi * 16 + arow) * SPITCH + kk * 16 + acol);
#pragma unroll
            for (int x = 0; x < 4; ++x)
                ldm_x4(bf[x], st + B_OFF + (nw + x * 16 + brow) * SPITCH + kk * 16 + bcol);
#pragma unroll
            for (int mi = 0; mi < 4; ++mi) {
#pragma unroll
                for (int nj = 0; nj < 8; ++nj) {
                    const int x = nj >> 1, y = (nj & 1) * 2;
                    mma16816h(c[mi][nj], af[mi][0], af[mi][1], af[mi][2], af[mi][3],
                              bf[x][y], bf[x][y + 1]);
                }
            }
        }
        __syncthreads();
    }

    // epilogue
#pragma unroll
    for (int mi = 0; mi < 4; ++mi) {
#pragma unroll
        for (int nj = 0; nj < 8; ++nj) {
            const int m = bm + mw + mi * 16 + (lane >> 2);
            const int n = bn + nw + nj * 8 + 2 * (lane & 3);
            if (MODE == 1) {
                *(float2*)(out + (size_t)m * 2048 + n) =
                    make_float2(c[mi][nj][0], c[mi][nj][1]);
                *(float2*)(out + (size_t)(m + 8) * 2048 + n) =
                    make_float2(c[mi][nj][2], c[mi][nj][3]);
            } else {
                const int b = m >> 11, t = m & 2047;
                const int d = n & 127;
                __half* dst;
                if (n < 2048) {
                    dst = g_qh + ((size_t)(b * NH + (n >> 7)) * TT + t) * HD + d;
                } else if (n < 2560) {
                    dst = g_kh + ((size_t)(b * NKV + ((n - 2048) >> 7)) * TT + t) * HD + d;
                } else {
                    dst = g_vh + ((size_t)(b * NKV + ((n - 2560) >> 7)) * TT + t) * HD + d;
                }
                *(unsigned*)dst            = packf16(c[mi][nj][0], c[mi][nj][1]);
                *(unsigned*)(dst + 8 * HD) = packf16(c[mi][nj][2], c[mi][nj][3]);
            }
        }
    }
}

// ---------------------------------------------------------------------------
// Vectorized RoPE in place on fp16 g_qh (scaled by 1/sqrt(HD)*log2e) and g_kh.
// Each thread handles 8 (d, d+64) pairs via uint4 loads/stores.
// ---------------------------------------------------------------------------
__global__ void rope_kernel(const float* __restrict__ cosp,
                            const float* __restrict__ sinp)
{
    const int i = blockIdx.x * 256 + threadIdx.x;
    const int nq8 = BB * NH * TT * 8;    // 524288
    const int nk8 = BB * NKV * TT * 8;   // 131072
    __half* base;
    int t;
    float sc;
    if (i < nq8) {
        const int row = i >> 3;
        t = row & 2047;
        base = g_qh + (size_t)row * HD;
        sc = 0.08838834764831845f * 1.44269504088896341f;
    } else if (i < nq8 + nk8) {
        const int row = (i - nq8) >> 3;
        t = row & 2047;
        base = g_kh + (size_t)row * HD;
        sc = 1.f;
    } else return;

    const int d8 = (i & 7) * 8;
    __half lo[8], hi[8];
    *(uint4*)lo = *(const uint4*)(base + d8);
    *(uint4*)hi = *(const uint4*)(base + d8 + 64);

    float c0[8], s0[8], c1[8], s1[8];
    *(float4*)&c0[0] = *(const float4*)&cosp[t * HD + d8];
    *(float4*)&c0[4] = *(const float4*)&cosp[t * HD + d8 + 4];
    *(float4*)&s0[0] = *(const float4*)&sinp[t * HD + d8];
    *(float4*)&s0[4] = *(const float4*)&sinp[t * HD + d8 + 4];
    *(float4*)&c1[0] = *(const float4*)&cosp[t * HD + d8 + 64];
    *(float4*)&c1[4] = *(const float4*)&cosp[t * HD + d8 + 68];
    *(float4*)&s1[0] = *(const float4*)&sinp[t * HD + d8 + 64];
    *(float4*)&s1[4] = *(const float4*)&sinp[t * HD + d8 + 68];

#pragma unroll
    for (int e = 0; e < 8; ++e) {
        const float x0 = __half2float(lo[e]);
        const float x1 = __half2float(hi[e]);
        lo[e] = __float2half((x0 * c0[e] - x1 * s0[e]) * sc);
        hi[e] = __float2half((x1 * c1[e] + x0 * s1[e]) * sc);
    }
    *(uint4*)(base + d8)      = *(uint4*)lo;
    *(uint4*)(base + d8 + 64) = *(uint4*)hi;
}

// ---------------------------------------------------------------------------
// Tensor-core flash attention: 128 q-rows x 128-key tiles, 2-stage cp.async
// ring (R12 code, exact group accounting).
// ---------------------------------------------------------------------------
#define APITCH 136
#define KS_ROW 128
#define VS_ROW (128 + 2 * 128)
#define ATT_SMEM_BYTES (640 * APITCH * 2)

__global__ __launch_bounds__(256, 1) void attn_tc()
{
    extern __shared__ __half sh2[];
    __half* sQ = sh2;

    const int tid = threadIdx.x;
    const int wid = tid >> 5, lane = tid & 31;
    const int r = lane >> 2, cq = lane & 3;
    const int qt = (int)gridDim.x - 1 - (int)blockIdx.x;   // heavy first
    const int bh = blockIdx.y;
    const int b = bh >> 4, h = bh & 15, kvh = h >> 2;

    const uint4* qg = (const uint4*)(g_qh + (size_t)bh * TT * HD + (size_t)qt * 128 * HD);
    const __half* kgp = g_kh + (size_t)(b * NKV + kvh) * TT * HD;
    const __half* vgp = g_vh + (size_t)(b * NKV + kvh) * TT * HD;
    const uint32_t sbatt = smem_u32(sh2);

#define ISSUE_KV(kt)                                                            \
    do {                                                                        \
        const int _s = (kt) & 1;                                                \
        _Pragma("unroll")                                                       \
        for (int _i = 0; _i < 8; ++_i) {                                        \
            const int _idx = _i * 256 + tid;                                    \
            const int _r = _idx >> 4, _c = (_idx & 15) * 8;                     \
            cpasync16(sbatt + ((KS_ROW + _s * 128 + _r) * APITCH + _c) * 2,     \
                      kgp + (size_t)((kt) * 128 + _r) * HD + _c);               \
            cpasync16(sbatt + ((VS_ROW + _s * 128 + _r) * APITCH + _c) * 2,     \
                      vgp + (size_t)((kt) * 128 + _r) * HD + _c);               \
        }                                                                       \
        CP_COMMIT();                                                            \
    } while (0)

#pragma unroll
    for (int it = 0; it < 8; ++it) {
        const int idx = it * 256 + tid;
        *(uint4*)&sQ[(idx >> 4) * APITCH + (idx & 15) * 8] = qg[idx];
    }

    const int ntiles = qt + 1;
    ISSUE_KV(0);
    if (ntiles > 1) ISSUE_KV(1);
    __syncthreads();

    unsigned qf[8][4];
    {
        const int arow = wid * 16 + (lane & 15);
        const int acol = (lane >> 4) * 8;
#pragma unroll
        for (int kk = 0; kk < 8; ++kk)
            ldm_x4(qf[kk], sQ + arow * APITCH + kk * 16 + acol);
    }

    float o[16][4];
#pragma unroll
    for (int nj = 0; nj < 16; ++nj)
#pragma unroll
        for (int e = 0; e < 4; ++e) o[nj][e] = 0.f;
    float m0 = -1e30f, m1 = -1e30f, l0 = 0.f, l1 = 0.f;

    const int krow = (lane & 7) + ((lane >> 4) << 3);
    const int kcol = ((lane >> 3) & 1) * 8;
    const int vrow = lane & 15;
    const int vcol = (lane >> 4) * 8;

    for (int kt = 0; kt < ntiles; ++kt) {
        if (kt + 1 < ntiles) cp_wait<1>();
        else                 cp_wait<0>();
        __syncthreads();

        __half* sK = sh2 + (KS_ROW + (kt & 1) * 128) * APITCH;
        __half* sV = sh2 + (VS_ROW + (kt & 1) * 128) * APITCH;

        float s[16][4];
#pragma unroll
        for (int nj = 0; nj < 16; ++nj)
#pragma unroll
            for (int e = 0; e < 4; ++e) s[nj][e] = 0.f;

#pragma unroll
        for (int kk = 0; kk < 8; ++kk) {
#pragma unroll
            for (int nb = 0; nb < 8; ++nb) {
                unsigned kf[4];
                ldm_x4(kf, sK + (nb * 16 + krow) * APITCH + kk * 16 + kcol);
                mma16816h(s[nb * 2],     qf[kk][0], qf[kk][1], qf[kk][2], qf[kk][3], kf[0], kf[1]);
                mma16816h(s[nb * 2 + 1], qf[kk][0], qf[kk][1], qf[kk][2], qf[kk][3], kf[2], kf[3]);
            }
        }

        if (kt + 1 == ntiles) {
            const int row0 = qt * 128 + wid * 16 + r;
#pragma unroll
            for (int nj = 0; nj < 16; ++nj) {
                const int key = kt * 128 + nj * 8 + 2 * cq;
                if (key > row0)         s[nj][0] = -1e30f;
                if (key + 1 > row0)     s[nj][1] = -1e30f;
                if (key > row0 + 8)     s[nj][2] = -1e30f;
                if (key + 1 > row0 + 8) s[nj][3] = -1e30f;
            }
        }

        float mx0 = s[0][0], mx1 = s[0][2];
#pragma unroll
        for (int nj = 0; nj < 16; ++nj) {
            mx0 = fmaxf(mx0, fmaxf(s[nj][0], s[nj][1]));
            mx1 = fmaxf(mx1, fmaxf(s[nj][2], s[nj][3]));
        }
        mx0 = fmaxf(mx0, __shfl_xor_sync(0xffffffffu, mx0, 1));
        mx0 = fmaxf(mx0, __shfl_xor_sync(0xffffffffu, mx0, 2));
        mx1 = fmaxf(mx1, __shfl_xor_sync(0xffffffffu, mx1, 1));
        mx1 = fmaxf(mx1, __shfl_xor_sync(0xffffffffu, mx1, 2));

        const float mn0 = fmaxf(m0, mx0), mn1 = fmaxf(m1, mx1);
        const float cr0 = ex2(m0 - mn0),  cr1 = ex2(m1 - mn1);
        m0 = mn0; m1 = mn1;

        float sum0 = 0.f, sum1 = 0.f;
#pragma unroll
        for (int nj = 0; nj < 16; ++nj) {
            s[nj][0] = ex2(s[nj][0] - mn0); sum0 += s[nj][0];
            s[nj][1] = ex2(s[nj][1] - mn0); sum0 += s[nj][1];
            s[nj][2] = ex2(s[nj][2] - mn1); sum1 += s[nj][2];
            s[nj][3] = ex2(s[nj][3] - mn1); sum1 += s[nj][3];
        }
        sum0 += __shfl_xor_sync(0xffffffffu, sum0, 1);
        sum0 += __shfl_xor_sync(0xffffffffu, sum0, 2);
        sum1 += __shfl_xor_sync(0xffffffffu, sum1, 1);
        sum1 += __shfl_xor_sync(0xffffffffu, sum1, 2);
        l0 = l0 * cr0 + sum0;
        l1 = l1 * cr1 + sum1;

#pragma unroll
        for (int nj = 0; nj < 16; ++nj) {
            o[nj][0] *= cr0; o[nj][1] *= cr0;
            o[nj][2] *= cr1; o[nj][3] *= cr1;
        }

        unsigned p[16][2];
#pragma unroll
        for (int nj = 0; nj < 16; ++nj) {
            p[nj][0] = packf16(s[nj][0], s[nj][1]);
            p[nj][1] = packf16(s[nj][2], s[nj][3]);
        }

#pragma unroll
        for (int kk = 0; kk < 8; ++kk) {
            const unsigned a0 = p[2 * kk][0],     a1 = p[2 * kk][1];
            const unsigned a2 = p[2 * kk + 1][0], a3 = p[2 * kk + 1][1];
#pragma unroll
            for (int db = 0; db < 8; ++db) {
                unsigned vf[4];
                ldm_x4_t(vf, sV + (kk * 16 + vrow) * APITCH + db * 16 + vcol);
                mma16816h(o[db * 2],     a0, a1, a2, a3, vf[0], vf[1]);
                mma16816h(o[db * 2 + 1], a0, a1, a2, a3, vf[2], vf[3]);
            }
        }
        __syncthreads();
        if (kt + 2 < ntiles) ISSUE_KV(kt + 2);
    }

    const float inv0 = 1.f / l0, inv1 = 1.f / l1;
    const int row0 = qt * 128 + wid * 16 + r;
    const size_t base0 = ((size_t)(b * TT + row0)) * CCH + h * HD;
    const size_t base1 = base0 + 8 * CCH;
#pragma unroll
    for (int nj = 0; nj < 16; ++nj) {
        const int d = nj * 8 + 2 * cq;
        *(unsigned*)(g_ah + base0 + d) = packf16(o[nj][0] * inv0, o[nj][1] * inv0);
        *(unsigned*)(g_ah + base1 + d) = packf16(o[nj][2] * inv1, o[nj][3] * inv1);
    }
}

// ---------------------------------------------------------------------------
extern "C" void kernel_launch(void* const* d_in, const int* in_sizes, int n_in,
                              void* d_out, int out_size)
{
    const float* x    = (const float*)d_in[0];
    const float* cosp = (const float*)d_in[1];
    const float* sinp = (const float*)d_in[2];
    const float* Wq   = (const float*)d_in[3];
    const float* Wk   = (const float*)d_in[4];
    const float* Wv   = (const float*)d_in[5];
    const float* Wo   = (const float*)d_in[6];
    float* out = (float*)d_out;

    cudaFuncSetAttribute(attn_tc,
                         cudaFuncAttributeMaxDynamicSharedMemorySize, ATT_SMEM_BYTES);
    cudaFuncSetAttribute(gemm_f16<0>,
                         cudaFuncAttributeMaxDynamicSharedMemorySize, G_SMEM_BYTES);
    cudaFuncSetAttribute(gemm_f16<1>,
                         cudaFuncAttributeMaxDynamicSharedMemorySize, G_SMEM_BYTES);

    // 0. conversions
    cvt_x_kernel<<<(MTOT * CCH / 4) / 256, 256>>>(x);
    t_wqkv<<<dim3(NQKV / 32, CCH / 32), 256>>>(Wq, Wk, Wv);
    t_wo<<<dim3(CCH / 32, CCH / 32), 256>>>(Wo);

    // 1. fused QKV projection -> fp16 q/k/v
    gemm_f16<0><<<dim3(NQKV / 256, MTOT / 128), 256, G_SMEM_BYTES>>>(nullptr);

    // 2. RoPE in place (fp16, vectorized)
    rope_kernel<<<(BB * NH * TT * 8 + BB * NKV * TT * 8) / 256, 256>>>(cosp, sinp);

    // 3. tensor-core causal GQA flash attention (128-key tiles)
    attn_tc<<<dim3(TT / 128, BB * NH), 256, ATT_SMEM_BYTES>>>();

    // 4. output projection
    gemm_f16<1><<<dim3(CCH / 256, MTOT / 128), 256, G_SMEM_BYTES>>>(out);
}

// round 16
// speedup vs baseline: 1.1944x; 1.0770x over previous
#include <cuda_runtime.h>
#include <cuda_fp16.h>
#include <cstdint>

#define BB 2
#define TT 2048
#define CCH 2048
#define NH 16
#define NKV 4
#define HD 128
#define MTOT 4096
#define NQKV 3072

// ---- scratch (no cudaMalloc allowed) ----
__device__ __half g_xh[(size_t)MTOT*CCH];      // x fp16 [m][k]
__device__ __half g_wqkv[(size_t)NQKV*CCH];    // W^T fp16 [n][k]
__device__ __half g_wo[(size_t)CCH*CCH];       // Wo^T fp16 [n][k]
__device__ __half g_ah[(size_t)MTOT*CCH];      // attn out fp16 [m][k]
__device__ __half g_qh[(size_t)BB*NH*TT*HD];
__device__ __half g_kh[(size_t)BB*NKV*TT*HD];
__device__ __half g_vh[(size_t)BB*NKV*TT*HD];

// ---------------------------------------------------------------------------
// Fused conversion kernel.
// blockIdx.y == 0 : x fp32 -> fp16          (8192 blocks used)
// blockIdx.y == 1 : Wq|Wk|Wv transpose      (96 x 64 tiles -> 6144 blocks)
// blockIdx.y == 2 : Wo transpose            (64 x 64 tiles -> 4096 blocks)
// gridDim.x = 8192 covers all three roles.
// ---------------------------------------------------------------------------
__global__ void fused_cvt(const float* __restrict__ x,
                          const float* __restrict__ Wq,
                          const float* __restrict__ Wk,
                          const float* __restrict__ Wv,
                          const float* __restrict__ Wo)
{
    const int role = blockIdx.y;
    if (role == 0) {
        const size_t i = (size_t)blockIdx.x * 256 + threadIdx.x;
        const float4 v = ((const float4*)x)[i];
        ((__half2*)g_xh)[2 * i]     = __floats2half2_rn(v.x, v.y);
        ((__half2*)g_xh)[2 * i + 1] = __floats2half2_rn(v.z, v.w);
        return;
    }

    __shared__ float tile[32][33];
    const int tx = threadIdx.x & 31, ty = threadIdx.x >> 5;

    if (role == 1) {
        if (blockIdx.x >= (NQKV / 32) * (CCH / 32)) return;
        const int n0 = (blockIdx.x % (NQKV / 32)) * 32;
        const int k0 = (blockIdx.x / (NQKV / 32)) * 32;
#pragma unroll
        for (int p = 0; p < 4; ++p) {
            const int r = ty + p * 8;
            const int n = n0 + tx;
            float v;
            if (n0 < 2048)      v = Wq[(size_t)(k0 + r) * 2048 + n];
            else if (n0 < 2560) v = Wk[(size_t)(k0 + r) * 512 + (n - 2048)];
            else                v = Wv[(size_t)(k0 + r) * 512 + (n - 2560)];
            tile[r][tx] = v;
        }
        __syncthreads();
#pragma unroll
        for (int p = 0; p < 4; ++p) {
            const int a = ty + p * 8;
            g_wqkv[(size_t)(n0 + a) * 2048 + k0 + tx] = __float2half(tile[tx][a]);
        }
    } else {
        if (blockIdx.x >= (CCH / 32) * (CCH / 32)) return;
        const int n0 = (blockIdx.x % (CCH / 32)) * 32;
        const int k0 = (blockIdx.x / (CCH / 32)) * 32;
#pragma unroll
        for (int p = 0; p < 4; ++p) {
            const int r = ty + p * 8;
            tile[r][tx] = Wo[(size_t)(k0 + r) * 2048 + n0 + tx];
        }
        __syncthreads();
#pragma unroll
        for (int p = 0; p < 4; ++p) {
            const int a = ty + p * 8;
            g_wo[(size_t)(n0 + a) * 2048 + k0 + tx] = __float2half(tile[tx][a]);
        }
    }
}

// ---------------------------------------------------------------------------
// Helpers
// ---------------------------------------------------------------------------
__device__ __forceinline__ uint32_t smem_u32(const void* p) {
    return (uint32_t)__cvta_generic_to_shared(p);
}
__device__ __forceinline__ void ldm_x4(unsigned r[4], const void* p) {
    uint32_t a = smem_u32(p);
    asm volatile("ldmatrix.sync.aligned.m8n8.x4.shared.b16 {%0,%1,%2,%3}, [%4];"
        : "=r"(r[0]), "=r"(r[1]), "=r"(r[2]), "=r"(r[3]) : "r"(a));
}
__device__ __forceinline__ void ldm_x4_t(unsigned r[4], const void* p) {
    uint32_t a = smem_u32(p);
    asm volatile("ldmatrix.sync.aligned.m8n8.x4.trans.shared.b16 {%0,%1,%2,%3}, [%4];"
        : "=r"(r[0]), "=r"(r[1]), "=r"(r[2]), "=r"(r[3]) : "r"(a));
}
__device__ __forceinline__ void mma16816h(float c[4],
    unsigned a0, unsigned a1, unsigned a2, unsigned a3, unsigned b0, unsigned b1)
{
    asm volatile(
        "mma.sync.aligned.m16n8k16.row.col.f32.f16.f16.f32 "
        "{%0,%1,%2,%3},{%4,%5,%6,%7},{%8,%9},{%0,%1,%2,%3};"
        : "+f"(c[0]), "+f"(c[1]), "+f"(c[2]), "+f"(c[3])
        : "r"(a0), "r"(a1), "r"(a2), "r"(a3), "r"(b0), "r"(b1));
}
__device__ __forceinline__ unsigned packf16(float lo, float hi) {
    unsigned d;
    asm("cvt.rn.f16x2.f32 %0, %1, %2;" : "=r"(d) : "f"(hi), "f"(lo));
    return d;
}
__device__ __forceinline__ float ex2(float x) {
    float y; asm("ex2.approx.f32 %0, %1;" : "=f"(y) : "f"(x)); return y;
}
__device__ __forceinline__ void cpasync16(uint32_t smem, const void* gmem) {
    asm volatile("cp.async.cg.shared.global [%0], [%1], 16;" :: "r"(smem), "l"(gmem));
}
#define CP_COMMIT() asm volatile("cp.async.commit_group;")
template<int N> __device__ __forceinline__ void cp_wait() {
    asm volatile("cp.async.wait_group %0;" :: "n"(N));
}

// ---------------------------------------------------------------------------
// Plain fp16 GEMM: CTA 128(M) x 256(N), BK=128, 256 threads (8 warps 2x4,
// warp tile 64x64). 2-stage cp.async ring (exact group accounting). R12 code.
// ---------------------------------------------------------------------------
#define SPITCH 136
#define A_OFF 0
#define B_OFF (128 * SPITCH)
#define STG_HALVES (384 * SPITCH)
#define G_SMEM_BYTES (2 * STG_HALVES * 2)   // 204 KB

template<int MODE>
__global__ __launch_bounds__(256, 1) void gemm_f16(float* __restrict__ out)
{
    extern __shared__ __half sgm[];

    const int tid  = threadIdx.x;
    const int lane = tid & 31;
    const int wid  = tid >> 5;
    const int bm = blockIdx.y * 128;
    const int bn = blockIdx.x * 256;
    const int mw = (wid >> 2) * 64;
    const int nw = (wid & 3) * 64;

    const __half* Ax = (MODE == 0) ? g_xh : g_ah;
    const __half* Bw = (MODE == 0) ? g_wqkv : g_wo;

    const uint32_t sb = smem_u32(sgm);

#define ISSUE(kt)                                                               \
    do {                                                                        \
        const int _k0 = (kt) * 128;                                             \
        const uint32_t _st = sb + (((kt) & 1) * STG_HALVES) * 2;                \
        _Pragma("unroll")                                                       \
        for (int _i = 0; _i < 8; ++_i) {                                        \
            const int _idx = _i * 256 + tid;                                    \
            const int _r = _idx >> 4, _c = (_idx & 15) * 8;                     \
            cpasync16(_st + (A_OFF + _r * SPITCH + _c) * 2,                     \
                      Ax + (size_t)(bm + _r) * CCH + _k0 + _c);                 \
        }                                                                       \
        _Pragma("unroll")                                                       \
        for (int _i = 0; _i < 16; ++_i) {                                       \
            const int _idx = _i * 256 + tid;                                    \
            const int _r = _idx >> 4, _c = (_idx & 15) * 8;                     \
            cpasync16(_st + (B_OFF + _r * SPITCH + _c) * 2,                     \
                      Bw + (size_t)(bn + _r) * CCH + _k0 + _c);                 \
        }                                                                       \
        CP_COMMIT();                                                            \
    } while (0)

    float c[4][8][4];
#pragma unroll
    for (int i = 0; i < 4; ++i)
#pragma unroll
        for (int j = 0; j < 8; ++j)
#pragma unroll
            for (int e = 0; e < 4; ++e) c[i][j][e] = 0.f;

    ISSUE(0);

    const int arow = ((lane >> 3) & 1) * 8 + (lane & 7);
    const int acol = (lane >> 4) * 8;
    const int brow = (lane >> 4) * 8 + (lane & 7);
    const int bcol = ((lane >> 3) & 1) * 8;

    const int NKT = CCH / 128;
    for (int kt = 0; kt < NKT; ++kt) {
        if (kt + 1 < NKT) { ISSUE(kt + 1); cp_wait<1>(); }
        else              { cp_wait<0>(); }
        __syncthreads();

        __half* st = sgm + (kt & 1) * STG_HALVES;
#pragma unroll
        for (int kk = 0; kk < 8; ++kk) {
            unsigned af[4][4], bf[4][4];
#pragma unroll
            for (int mi = 0; mi < 4; ++mi)
                ldm_x4(af[mi], st + A_OFF + (mw + mi * 16 + arow) * SPITCH + kk * 16 + acol);
#pragma unroll
            for (int x = 0; x < 4; ++x)
                ldm_x4(bf[x], st + B_OFF + (nw + x * 16 + brow) * SPITCH + kk * 16 + bcol);
#pragma unroll
            for (int mi = 0; mi < 4; ++mi) {
#pragma unroll
                for (int nj = 0; nj < 8; ++nj) {
                    const int x = nj >> 1, y = (nj & 1) * 2;
                    mma16816h(c[mi][nj], af[mi][0], af[mi][1], af[mi][2], af[mi][3],
                              bf[x][y], bf[x][y + 1]);
                }
            }
        }
        __syncthreads();
    }

    // epilogue
#pragma unroll
    for (int mi = 0; mi < 4; ++mi) {
#pragma unroll
        for (int nj = 0; nj < 8; ++nj) {
            const int m = bm + mw + mi * 16 + (lane >> 2);
            const int n = bn + nw + nj * 8 + 2 * (lane & 3);
            if (MODE == 1) {
                *(float2*)(out + (size_t)m * 2048 + n) =
                    make_float2(c[mi][nj][0], c[mi][nj][1]);
                *(float2*)(out + (size_t)(m + 8) * 2048 + n) =
                    make_float2(c[mi][nj][2], c[mi][nj][3]);
            } else {
                const int b = m >> 11, t = m & 2047;
                const int d = n & 127;
                __half* dst;
                if (n < 2048) {
                    dst = g_qh + ((size_t)(b * NH + (n >> 7)) * TT + t) * HD + d;
                } else if (n < 2560) {
                    dst = g_kh + ((size_t)(b * NKV + ((n - 2048) >> 7)) * TT + t) * HD + d;
                } else {
                    dst = g_vh + ((size_t)(b * NKV + ((n - 2560) >> 7)) * TT + t) * HD + d;
                }
                *(unsigned*)dst            = packf16(c[mi][nj][0], c[mi][nj][1]);
                *(unsigned*)(dst + 8 * HD) = packf16(c[mi][nj][2], c[mi][nj][3]);
            }
        }
    }
}

// ---------------------------------------------------------------------------
// Vectorized RoPE in place on fp16 g_qh (scaled by 1/sqrt(HD)*log2e) and g_kh.
// ---------------------------------------------------------------------------
__global__ void rope_kernel(const float* __restrict__ cosp,
                            const float* __restrict__ sinp)
{
    const int i = blockIdx.x * 256 + threadIdx.x;
    const int nq8 = BB * NH * TT * 8;
    const int nk8 = BB * NKV * TT * 8;
    __half* base;
    int t;
    float sc;
    if (i < nq8) {
        const int row = i >> 3;
        t = row & 2047;
        base = g_qh + (size_t)row * HD;
        sc = 0.08838834764831845f * 1.44269504088896341f;
    } else if (i < nq8 + nk8) {
        const int row = (i - nq8) >> 3;
        t = row & 2047;
        base = g_kh + (size_t)row * HD;
        sc = 1.f;
    } else return;

    const int d8 = (i & 7) * 8;
    __half lo[8], hi[8];
    *(uint4*)lo = *(const uint4*)(base + d8);
    *(uint4*)hi = *(const uint4*)(base + d8 + 64);

    float c0[8], s0[8], c1[8], s1[8];
    *(float4*)&c0[0] = *(const float4*)&cosp[t * HD + d8];
    *(float4*)&c0[4] = *(const float4*)&cosp[t * HD + d8 + 4];
    *(float4*)&s0[0] = *(const float4*)&sinp[t * HD + d8];
    *(float4*)&s0[4] = *(const float4*)&sinp[t * HD + d8 + 4];
    *(float4*)&c1[0] = *(const float4*)&cosp[t * HD + d8 + 64];
    *(float4*)&c1[4] = *(const float4*)&cosp[t * HD + d8 + 68];
    *(float4*)&s1[0] = *(const float4*)&sinp[t * HD + d8 + 64];
    *(float4*)&s1[4] = *(const float4*)&sinp[t * HD + d8 + 68];

#pragma unroll
    for (int e = 0; e < 8; ++e) {
        const float x0 = __half2float(lo[e]);
        const float x1 = __half2float(hi[e]);
        lo[e] = __float2half((x0 * c0[e] - x1 * s0[e]) * sc);
        hi[e] = __float2half((x1 * c1[e] + x0 * s1[e]) * sc);
    }
    *(uint4*)(base + d8)      = *(uint4*)lo;
    *(uint4*)(base + d8 + 64) = *(uint4*)hi;
}

// ---------------------------------------------------------------------------
// Tensor-core flash attention: 128 q-rows x 128-key tiles, 2-stage cp.async
// ring. Grid = (bh, qt_rev) so heaviest q-tiles of ALL heads schedule first.
// ---------------------------------------------------------------------------
#define APITCH 136
#define KS_ROW 128
#define VS_ROW (128 + 2 * 128)
#define ATT_SMEM_BYTES (640 * APITCH * 2)

__global__ __launch_bounds__(256, 1) void attn_tc()
{
    extern __shared__ __half sh2[];
    __half* sQ = sh2;

    const int tid = threadIdx.x;
    const int wid = tid >> 5, lane = tid & 31;
    const int r = lane >> 2, cq = lane & 3;
    const int qt = (int)gridDim.y - 1 - (int)blockIdx.y;   // heavy first, globally
    const int bh = blockIdx.x;
    const int b = bh >> 4, h = bh & 15, kvh = h >> 2;

    const uint4* qg = (const uint4*)(g_qh + (size_t)bh * TT * HD + (size_t)qt * 128 * HD);
    const __half* kgp = g_kh + (size_t)(b * NKV + kvh) * TT * HD;
    const __half* vgp = g_vh + (size_t)(b * NKV + kvh) * TT * HD;
    const uint32_t sbatt = smem_u32(sh2);

#define ISSUE_KV(kt)                                                            \
    do {                                                                        \
        const int _s = (kt) & 1;                                                \
        _Pragma("unroll")                                                       \
        for (int _i = 0; _i < 8; ++_i) {                                        \
            const int _idx = _i * 256 + tid;                                    \
            const int _r = _idx >> 4, _c = (_idx & 15) * 8;                     \
            cpasync16(sbatt + ((KS_ROW + _s * 128 + _r) * APITCH + _c) * 2,     \
                      kgp + (size_t)((kt) * 128 + _r) * HD + _c);               \
            cpasync16(sbatt + ((VS_ROW + _s * 128 + _r) * APITCH + _c) * 2,     \
                      vgp + (size_t)((kt) * 128 + _r) * HD + _c);               \
        }                                                                       \
        CP_COMMIT();                                                            \
    } while (0)

#pragma unroll
    for (int it = 0; it < 8; ++it) {
        const int idx = it * 256 + tid;
        *(uint4*)&sQ[(idx >> 4) * APITCH + (idx & 15) * 8] = qg[idx];
    }

    const int ntiles = qt + 1;
    ISSUE_KV(0);
    if (ntiles > 1) ISSUE_KV(1);
    __syncthreads();

    unsigned qf[8][4];
    {
        const int arow = wid * 16 + (lane & 15);
        const int acol = (lane >> 4) * 8;
#pragma unroll
        for (int kk = 0; kk < 8; ++kk)
            ldm_x4(qf[kk], sQ + arow * APITCH + kk * 16 + acol);
    }

    float o[16][4];
#pragma unroll
    for (int nj = 0; nj < 16; ++nj)
#pragma unroll
        for (int e = 0; e < 4; ++e) o[nj][e] = 0.f;
    float m0 = -1e30f, m1 = -1e30f, l0 = 0.f, l1 = 0.f;

    const int krow = (lane & 7) + ((lane >> 4) << 3);
    const int kcol = ((lane >> 3) & 1) * 8;
    const int vrow = lane & 15;
    const int vcol = (lane >> 4) * 8;

    for (int kt = 0; kt < ntiles; ++kt) {
        if (kt + 1 < ntiles) cp_wait<1>();
        else                 cp_wait<0>();
        __syncthreads();

        __half* sK = sh2 + (KS_ROW + (kt & 1) * 128) * APITCH;
        __half* sV = sh2 + (VS_ROW + (kt & 1) * 128) * APITCH;

        float s[16][4];
#pragma unroll
        for (int nj = 0; nj < 16; ++nj)
#pragma unroll
            for (int e = 0; e < 4; ++e) s[nj][e] = 0.f;

#pragma unroll
        for (int kk = 0; kk < 8; ++kk) {
#pragma unroll
            for (int nb = 0; nb < 8; ++nb) {
                unsigned kf[4];
                ldm_x4(kf, sK + (nb * 16 + krow) * APITCH + kk * 16 + kcol);
                mma16816h(s[nb * 2],     qf[kk][0], qf[kk][1], qf[kk][2], qf[kk][3], kf[0], kf[1]);
                mma16816h(s[nb * 2 + 1], qf[kk][0], qf[kk][1], qf[kk][2], qf[kk][3], kf[2], kf[3]);
            }
        }

        if (kt + 1 == ntiles) {
            const int row0 = qt * 128 + wid * 16 + r;
#pragma unroll
            for (int nj = 0; nj < 16; ++nj) {
                const int key = kt * 128 + nj * 8 + 2 * cq;
                if (key > row0)         s[nj][0] = -1e30f;
                if (key + 1 > row0)     s[nj][1] = -1e30f;
                if (key > row0 + 8)     s[nj][2] = -1e30f;
                if (key + 1 > row0 + 8) s[nj][3] = -1e30f;
            }
        }

        float mx0 = s[0][0], mx1 = s[0][2];
#pragma unroll
        for (int nj = 0; nj < 16; ++nj) {
            mx0 = fmaxf(mx0, fmaxf(s[nj][0], s[nj][1]));
            mx1 = fmaxf(mx1, fmaxf(s[nj][2], s[nj][3]));
        }
        mx0 = fmaxf(mx0, __shfl_xor_sync(0xffffffffu, mx0, 1));
        mx0 = fmaxf(mx0, __shfl_xor_sync(0xffffffffu, mx0, 2));
        mx1 = fmaxf(mx1, __shfl_xor_sync(0xffffffffu, mx1, 1));
        mx1 = fmaxf(mx1, __shfl_xor_sync(0xffffffffu, mx1, 2));

        const float mn0 = fmaxf(m0, mx0), mn1 = fmaxf(m1, mx1);
        const float cr0 = ex2(m0 - mn0),  cr1 = ex2(m1 - mn1);
        m0 = mn0; m1 = mn1;

        float sum0 = 0.f, sum1 = 0.f;
#pragma unroll
        for (int nj = 0; nj < 16; ++nj) {
            s[nj][0] = ex2(s[nj][0] - mn0); sum0 += s[nj][0];
            s[nj][1] = ex2(s[nj][1] - mn0); sum0 += s[nj][1];
            s[nj][2] = ex2(s[nj][2] - mn1); sum1 += s[nj][2];
            s[nj][3] = ex2(s[nj][3] - mn1); sum1 += s[nj][3];
        }
        sum0 += __shfl_xor_sync(0xffffffffu, sum0, 1);
        sum0 += __shfl_xor_sync(0xffffffffu, sum0, 2);
        sum1 += __shfl_xor_sync(0xffffffffu, sum1, 1);
        sum1 += __shfl_xor_sync(0xffffffffu, sum1, 2);
        l0 = l0 * cr0 + sum0;
        l1 = l1 * cr1 + sum1;

#pragma unroll
        for (int nj = 0; nj < 16; ++nj) {
            o[nj][0] *= cr0; o[nj][1] *= cr0;
            o[nj][2] *= cr1; o[nj][3] *= cr1;
        }

        unsigned p[16][2];
#pragma unroll
        for (int nj = 0; nj < 16; ++nj) {
            p[nj][0] = packf16(s[nj][0], s[nj][1]);
            p[nj][1] = packf16(s[nj][2], s[nj][3]);
        }

#pragma unroll
        for (int kk = 0; kk < 8; ++kk) {
            const unsigned a0 = p[2 * kk][0],     a1 = p[2 * kk][1];
            const unsigned a2 = p[2 * kk + 1][0], a3 = p[2 * kk + 1][1];
#pragma unroll
            for (int db = 0; db < 8; ++db) {
                unsigned vf[4];
                ldm_x4_t(vf, sV + (kk * 16 + vrow) * APITCH + db * 16 + vcol);
                mma16816h(o[db * 2],     a0, a1, a2, a3, vf[0], vf[1]);
                mma16816h(o[db * 2 + 1], a0, a1, a2, a3, vf[2], vf[3]);
            }
        }
        __syncthreads();
        if (kt + 2 < ntiles) ISSUE_KV(kt + 2);
    }

    const float inv0 = 1.f / l0, inv1 = 1.f / l1;
    const int row0 = qt * 128 + wid * 16 + r;
    const size_t base0 = ((size_t)(b * TT + row0)) * CCH + h * HD;
    const size_t base1 = base0 + 8 * CCH;
#pragma unroll
    for (int nj = 0; nj < 16; ++nj) {
        const int d = nj * 8 + 2 * cq;
        *(unsigned*)(g_ah + base0 + d) = packf16(o[nj][0] * inv0, o[nj][1] * inv0);
        *(unsigned*)(g_ah + base1 + d) = packf16(o[nj][2] * inv1, o[nj][3] * inv1);
    }
}

// ---------------------------------------------------------------------------
extern "C" void kernel_launch(void* const* d_in, const int* in_sizes, int n_in,
                              void* d_out, int out_size)
{
    const float* x    = (const float*)d_in[0];
    const float* cosp = (const float*)d_in[1];
    const float* sinp = (const float*)d_in[2];
    const float* Wq   = (const float*)d_in[3];
    const float* Wk   = (const float*)d_in[4];
    const float* Wv   = (const float*)d_in[5];
    const float* Wo   = (const float*)d_in[6];
    float* out = (float*)d_out;

    cudaFuncSetAttribute(attn_tc,
                         cudaFuncAttributeMaxDynamicSharedMemorySize, ATT_SMEM_BYTES);
    cudaFuncSetAttribute(gemm_f16<0>,
                         cudaFuncAttributeMaxDynamicSharedMemorySize, G_SMEM_BYTES);
    cudaFuncSetAttribute(gemm_f16<1>,
                         cudaFuncAttributeMaxDynamicSharedMemorySize, G_SMEM_BYTES);

    // 0. fused conversions (x cvt + both weight transposes in one launch)
    fused_cvt<<<dim3(MTOT * CCH / 4 / 256, 3), 256>>>(x, Wq, Wk, Wv, Wo);

    // 1. fused QKV projection -> fp16 q/k/v
    gemm_f16<0><<<dim3(NQKV / 256, MTOT / 128), 256, G_SMEM_BYTES>>>(nullptr);

    // 2. RoPE in place (fp16, vectorized)
    rope_kernel<<<(BB * NH * TT * 8 + BB * NKV * TT * 8) / 256, 256>>>(cosp, sinp);

    // 3. tensor-core causal GQA flash attention (globally heavy-first order)
    attn_tc<<<dim3(BB * NH, TT / 128), 256, ATT_SMEM_BYTES>>>();

    // 4. output projection
    gemm_f16<1><<<dim3(CCH / 256, MTOT / 128), 256, G_SMEM_BYTES>>>(out);
}